// round 9
// baseline (speedup 1.0000x reference)
#include <cuda_runtime.h>
#include <cstdint>

#define THREADS 256
#define ROWS_PER_BLOCK 256
#define OV_PITCH 264   // words; mod 32 == 8 -> A-frag loads conflict-free

// ---- smem word offsets ----
#define WHI_O   0          // 16*24*24 tf32-hi bits
#define WLO_O   9216       // tf32-lo bits
#define OVS_O   18432      // ov slab [24 cols][OV_PITCH] f32
#define XS_O    24768      // x stage 256*27 f32
#define WOUT_O  31680      // 24*3
#define BOUT_O  31752      // 3
#define SMEM_WORDS 31760   // 127,040 bytes

// ---- fast transcendentals (MUFU pipe) ----
__device__ __forceinline__ float softplus_fast(float x) {
    float e, l;
    float y = fabsf(x) * -1.4426950408889634f;
    asm("ex2.approx.f32 %0, %1;" : "=f"(e) : "f"(y));
    float u = 1.0f + e;
    asm("lg2.approx.f32 %0, %1;" : "=f"(l) : "f"(u));
    return fmaxf(x, 0.0f) + l * 0.6931471805599453f;
}
__device__ __forceinline__ float exp_fast(float x) {
    float e;
    asm("ex2.approx.f32 %0, %1;" : "=f"(e) : "f"(x * 1.4426950408889634f));
    return e;
}
__device__ __forceinline__ float rcp_fast(float x) {
    float r;
    asm("rcp.approx.f32 %0, %1;" : "=f"(r) : "f"(x));
    return r;
}
__device__ __forceinline__ uint32_t tf32_hi(float v) {
    uint32_t b;
    asm("cvt.rna.tf32.f32 %0, %1;" : "=r"(b) : "f"(v));
    return b;
}

// m16n8k8 tf32 MMA, accumulate in place.
// A frag: a0:(r,c) a1:(r+8,c) a2:(r,c+4) a3:(r+8,c+4), r=lane/4, c=lane%4
// B frag: b0:(k=lane%4, n=lane/4) b1:(k=lane%4+4, n=lane/4)
// C frag: c0:(r,2c) c1:(r,2c+1) c2:(r+8,2c) c3:(r+8,2c+1)
__device__ __forceinline__ void mma_tf32(float* d, const uint32_t* a,
                                         uint32_t b0, uint32_t b1) {
    asm volatile(
        "mma.sync.aligned.m16n8k8.row.col.f32.tf32.tf32.f32 "
        "{%0,%1,%2,%3}, {%4,%5,%6,%7}, {%8,%9}, {%0,%1,%2,%3};"
        : "+f"(d[0]), "+f"(d[1]), "+f"(d[2]), "+f"(d[3])
        : "r"(a[0]), "r"(a[1]), "r"(a[2]), "r"(a[3]), "r"(b0), "r"(b1));
}

// V element for (row, col) from staged x row pointer
__device__ __forceinline__ float v_col(const float* xr, int col,
                                       float bt, float bc,
                                       float a1, float a2, float a3) {
    if (col < 19) return xr[col];
    if (col == 19) return xr[21];
    if (col == 20) return xr[24];
    if (col == 21) return fmaf(bc, xr[20], fmaf(bt, xr[19], a1));
    if (col == 22) return fmaf(bc, xr[23], fmaf(bt, xr[22], a2));
    return fmaf(bc, xr[26], fmaf(bt, xr[25], a3));
}

__global__ __launch_bounds__(THREADS, 1)
void reslogit_mma_kernel(const float* __restrict__ x,
                         const float* __restrict__ asc_train,
                         const float* __restrict__ asc_sm,
                         const float* __restrict__ asc_car,
                         const float* __restrict__ b_time,
                         const float* __restrict__ b_cost,
                         const float* __restrict__ Ws,
                         const float* __restrict__ W_out,
                         const float* __restrict__ b_out,
                         float* __restrict__ out,
                         int B)
{
    extern __shared__ uint32_t sm[];
    float* smf = reinterpret_cast<float*>(sm);
    uint32_t* Whi = sm + WHI_O;
    uint32_t* Wlo = sm + WLO_O;
    float* ovS   = smf + OVS_O;
    float* xS    = smf + XS_O;
    float* sWout = smf + WOUT_O;
    float* sbout = smf + BOUT_O;

    const int tid  = threadIdx.x;
    const int row0 = blockIdx.x * ROWS_PER_BLOCK;

    // ---- stage x (coalesced), zero-fill tail ----
    {
        const float* xblk = x + (size_t)row0 * 27;
        int nrow = B - row0; if (nrow > ROWS_PER_BLOCK) nrow = ROWS_PER_BLOCK;
        const int nelem = nrow * 27;
        for (int i = tid; i < nelem; i += THREADS) xS[i] = xblk[i];
        for (int i = nelem + tid; i < ROWS_PER_BLOCK * 27; i += THREADS) xS[i] = 0.0f;
    }
    if (tid < 72) sWout[tid] = W_out[tid];
    if (tid < 3)  sbout[tid] = b_out[tid];

    // ---- split Ws into tf32 hi/lo (once per CTA) ----
    for (int e = tid; e < 9216; e += THREADS) {
        const float v = __ldg(&Ws[e]);
        const uint32_t hb = tf32_hi(v);
        Whi[e] = hb;
        Wlo[e] = tf32_hi(v - __uint_as_float(hb));
    }
    __syncthreads();

    const int lane  = tid & 31;
    const int g     = lane >> 2;      // groupID (row select)
    const int t     = lane & 3;       // threadID_in_group (col select)
    const int wbase = (tid >> 5) * 32; // warp's first local row

    const float bt = __ldg(b_time), bc = __ldg(b_cost);
    const float a1 = __ldg(asc_train), a2 = __ldg(asc_sm), a3 = __ldg(asc_car);

    // thread's 4 patch rows (local)
    int rloc[4];
    rloc[0] = wbase + g;       rloc[1] = wbase + g + 8;
    rloc[2] = wbase + 16 + g;  rloc[3] = wbase + 24 + g;

    // state in C-fragment patch layout: slot [m][n][c]
    //   row = rloc[m*2 + (c>>1)], col = 8n + 2t + (c&1)
    float ov[2][3][4], S[2][3][4];
    #pragma unroll
    for (int m = 0; m < 2; m++)
        #pragma unroll
        for (int n = 0; n < 3; n++)
            #pragma unroll
            for (int c = 0; c < 4; c++) {
                const int row = rloc[m * 2 + (c >> 1)];
                const int col = 8 * n + 2 * t + (c & 1);
                ov[m][n][c] = v_col(xS + row * 27, col, bt, bc, a1, a2, a3);
                S[m][n][c]  = 0.0f;
            }

    // publish ov_0 to slab
    #pragma unroll
    for (int m = 0; m < 2; m++)
        #pragma unroll
        for (int n = 0; n < 3; n++)
            #pragma unroll
            for (int c = 0; c < 4; c++) {
                const int row = rloc[m * 2 + (c >> 1)];
                const int col = 8 * n + 2 * t + (c & 1);
                ovS[col * OV_PITCH + row] = ov[m][n][c];
            }
    __syncwarp();

    // ---- 16-step scan ----
    #pragma unroll 1
    for (int k = 0; k < 16; k++) {
        const uint32_t* WH = Whi + k * 576;
        const uint32_t* WL = Wlo + k * 576;

        float D[2][3][4];
        #pragma unroll
        for (int m = 0; m < 2; m++)
            #pragma unroll
            for (int n = 0; n < 3; n++)
                #pragma unroll
                for (int c = 0; c < 4; c++) D[m][n][c] = 0.0f;

        #pragma unroll
        for (int kk = 0; kk < 3; kk++) {
            // A fragments (hi + lo) for both M-tiles from the ov slab
            uint32_t ahi[2][4], alo[2][4];
            #pragma unroll
            for (int m = 0; m < 2; m++) {
                const int ra = wbase + m * 16 + g;
                #pragma unroll
                for (int q = 0; q < 4; q++) {
                    const int col = 8 * kk + t + (q >> 1) * 4;
                    const int row = ra + (q & 1) * 8;
                    const float v = ovS[col * OV_PITCH + row];
                    const uint32_t hb = tf32_hi(v);
                    ahi[m][q] = hb;
                    alo[m][q] = tf32_hi(v - __uint_as_float(hb));
                }
            }
            #pragma unroll
            for (int n = 0; n < 3; n++) {
                const int bi = (8 * kk + t) * 24 + 8 * n + g;
                const uint32_t bh0 = WH[bi], bh1 = WH[bi + 96];  // +4 k-rows
                const uint32_t bl0 = WL[bi], bl1 = WL[bi + 96];
                #pragma unroll
                for (int m = 0; m < 2; m++) {
                    mma_tf32(D[m][n], ahi[m], bh0, bh1);   // hi*hi
                    mma_tf32(D[m][n], alo[m], bh0, bh1);   // lo*hi
                    mma_tf32(D[m][n], ahi[m], bl0, bl1);   // hi*lo
                }
            }
        }
        __syncwarp();   // all A reads done before slab overwrite

        // softplus + running-sum scan update, elementwise in patch layout
        #pragma unroll
        for (int m = 0; m < 2; m++)
            #pragma unroll
            for (int n = 0; n < 3; n++)
                #pragma unroll
                for (int c = 0; c < 4; c++) {
                    S[m][n][c] += softplus_fast(D[m][n][c]);
                    ov[m][n][c] -= S[m][n][c];
                }

        if (k < 15) {
            #pragma unroll
            for (int m = 0; m < 2; m++)
                #pragma unroll
                for (int n = 0; n < 3; n++)
                    #pragma unroll
                    for (int c = 0; c < 4; c++) {
                        const int row = rloc[m * 2 + (c >> 1)];
                        const int col = 8 * n + 2 * t + (c & 1);
                        ovS[col * OV_PITCH + row] = ov[m][n][c];
                    }
            __syncwarp();
        }
    }

    // ---- epilogue: U = V - S_16, softmax(24), @W_out + b_out, relu ----
    float u[2][3][4];
    #pragma unroll
    for (int m = 0; m < 2; m++)
        #pragma unroll
        for (int n = 0; n < 3; n++)
            #pragma unroll
            for (int c = 0; c < 4; c++) {
                const int row = rloc[m * 2 + (c >> 1)];
                const int col = 8 * n + 2 * t + (c & 1);
                u[m][n][c] = v_col(xS + row * 27, col, bt, bc, a1, a2, a3) - S[m][n][c];
            }

    #pragma unroll
    for (int rr = 0; rr < 4; rr++) {
        const int m = rr >> 1, ch = rr & 1;

        float mx = -3.4e38f;
        #pragma unroll
        for (int n = 0; n < 3; n++)
            #pragma unroll
            for (int p = 0; p < 2; p++) mx = fmaxf(mx, u[m][n][ch * 2 + p]);
        mx = fmaxf(mx, __shfl_xor_sync(0xffffffffu, mx, 1));
        mx = fmaxf(mx, __shfl_xor_sync(0xffffffffu, mx, 2));

        float e[6], s = 0.0f;
        #pragma unroll
        for (int n = 0; n < 3; n++)
            #pragma unroll
            for (int p = 0; p < 2; p++) {
                const float ev = exp_fast(u[m][n][ch * 2 + p] - mx);
                e[n * 2 + p] = ev;
                s += ev;
            }
        s += __shfl_xor_sync(0xffffffffu, s, 1);
        s += __shfl_xor_sync(0xffffffffu, s, 2);
        const float inv = rcp_fast(s);

        float d0 = 0.0f, d1 = 0.0f, d2 = 0.0f;
        #pragma unroll
        for (int n = 0; n < 3; n++)
            #pragma unroll
            for (int p = 0; p < 2; p++) {
                const int col = 8 * n + 2 * t + p;
                const float ev = e[n * 2 + p];
                d0 = fmaf(ev, sWout[col * 3 + 0], d0);
                d1 = fmaf(ev, sWout[col * 3 + 1], d1);
                d2 = fmaf(ev, sWout[col * 3 + 2], d2);
            }
        d0 += __shfl_xor_sync(0xffffffffu, d0, 1);
        d0 += __shfl_xor_sync(0xffffffffu, d0, 2);
        d1 += __shfl_xor_sync(0xffffffffu, d1, 1);
        d1 += __shfl_xor_sync(0xffffffffu, d1, 2);
        d2 += __shfl_xor_sync(0xffffffffu, d2, 1);
        d2 += __shfl_xor_sync(0xffffffffu, d2, 2);

        if (t == 0) {
            const int grow = row0 + rloc[rr];
            if (grow < B) {
                float* op = out + (size_t)grow * 3;
                op[0] = fmaxf(fmaf(d0, inv, sbout[0]), 0.0f);
                op[1] = fmaxf(fmaf(d1, inv, sbout[1]), 0.0f);
                op[2] = fmaxf(fmaf(d2, inv, sbout[2]), 0.0f);
            }
        }
    }
}

extern "C" void kernel_launch(void* const* d_in, const int* in_sizes, int n_in,
                              void* d_out, int out_size)
{
    const float* x         = (const float*)d_in[0];
    const float* asc_train = (const float*)d_in[1];
    const float* asc_sm    = (const float*)d_in[2];
    const float* asc_car   = (const float*)d_in[3];
    const float* b_time    = (const float*)d_in[4];
    const float* b_cost    = (const float*)d_in[5];
    const float* Ws        = (const float*)d_in[6];
    const float* W_out     = (const float*)d_in[7];
    const float* b_out     = (const float*)d_in[8];
    float* out = (float*)d_out;

    const int B = in_sizes[0] / 27;
    const int smem_bytes = SMEM_WORDS * 4;

    cudaFuncSetAttribute(reslogit_mma_kernel,
                         cudaFuncAttributeMaxDynamicSharedMemorySize, smem_bytes);

    const int grid = (B + ROWS_PER_BLOCK - 1) / ROWS_PER_BLOCK;
    reslogit_mma_kernel<<<grid, THREADS, smem_bytes>>>(
        x, asc_train, asc_sm, asc_car, b_time, b_cost, Ws, W_out, b_out, out, B);
}

// round 10
// speedup vs baseline: 1.7249x; 1.7249x over previous
#include <cuda_runtime.h>
#include <cstdint>

#define THREADS 256
#define ROWS_PER_BLOCK 256

// ---- smem word offsets ----
// W packed bf16x2 pairs, B-operand layout [step][n=24][pair pad 20]
#define WPHI_O  0                    // 16*480 = 7680
#define WPLO_O  7680                 // 7680
#define OVHI_O  15360                // ov slab hi: [16 pairs][264]
#define OVLO_O  (15360 + 4224)      // ov slab lo
#define WOUT_O  (15360 + 8448)      // 24*3
#define BOUT_O  (WOUT_O + 72)
#define SMEM_WORDS (BOUT_O + 4)     // 23836 words = 95,344 B -> 2 CTAs/SM

#define OVP 264   // slab pitch; 264 % 32 == 8 -> conflict-free for (t,g) pattern
#define WNP 20    // W pair pitch; 20g % 32 spans multiples of 4 -> conflict-free

// ---- packing helpers ----
// d = {hi16 = bf16(vh), lo16 = bf16(vl)}
#define PACK_BF16X2(d, vh, vl) \
    asm("cvt.rn.bf16x2.f32 %0, %1, %2;" : "=r"(d) : "f"(vh), "f"(vl))
__device__ __forceinline__ float bf_lo_f32(uint32_t p) { return __uint_as_float(p << 16); }
__device__ __forceinline__ float bf_hi_f32(uint32_t p) { return __uint_as_float(p & 0xffff0000u); }

// ---- fast transcendentals (MUFU pipe) ----
__device__ __forceinline__ float softplus_fast(float x) {
    float e, l;
    float y = fabsf(x) * -1.4426950408889634f;
    asm("ex2.approx.f32 %0, %1;" : "=f"(e) : "f"(y));
    float u = 1.0f + e;
    asm("lg2.approx.f32 %0, %1;" : "=f"(l) : "f"(u));
    return fmaxf(x, 0.0f) + l * 0.6931471805599453f;
}
__device__ __forceinline__ float exp_fast(float x) {
    float e;
    asm("ex2.approx.f32 %0, %1;" : "=f"(e) : "f"(x * 1.4426950408889634f));
    return e;
}
__device__ __forceinline__ float rcp_fast(float x) {
    float r;
    asm("rcp.approx.f32 %0, %1;" : "=f"(r) : "f"(x));
    return r;
}

// m16n8k16 bf16 MMA, f32 accumulate in place
__device__ __forceinline__ void mma_bf16(float* d, const uint32_t* a,
                                         uint32_t b0, uint32_t b1) {
    asm volatile(
        "mma.sync.aligned.m16n8k16.row.col.f32.bf16.bf16.f32 "
        "{%0,%1,%2,%3}, {%4,%5,%6,%7}, {%8,%9}, {%0,%1,%2,%3};"
        : "+f"(d[0]), "+f"(d[1]), "+f"(d[2]), "+f"(d[3])
        : "r"(a[0]), "r"(a[1]), "r"(a[2]), "r"(a[3]), "r"(b0), "r"(b1));
}

// V element for (global row, col)
__device__ __forceinline__ float v_col(const float* __restrict__ xr, int col,
                                       float bt, float bc,
                                       float a1, float a2, float a3) {
    if (col < 19) return __ldg(&xr[col]);
    if (col == 19) return __ldg(&xr[21]);
    if (col == 20) return __ldg(&xr[24]);
    if (col == 21) return fmaf(bc, __ldg(&xr[20]), fmaf(bt, __ldg(&xr[19]), a1));
    if (col == 22) return fmaf(bc, __ldg(&xr[23]), fmaf(bt, __ldg(&xr[22]), a2));
    return fmaf(bc, __ldg(&xr[26]), fmaf(bt, __ldg(&xr[25]), a3));
}

__global__ __launch_bounds__(THREADS, 2)
void reslogit_bf16_kernel(const float* __restrict__ x,
                          const float* __restrict__ asc_train,
                          const float* __restrict__ asc_sm,
                          const float* __restrict__ asc_car,
                          const float* __restrict__ b_time,
                          const float* __restrict__ b_cost,
                          const float* __restrict__ Ws,
                          const float* __restrict__ W_out,
                          const float* __restrict__ b_out,
                          float* __restrict__ out,
                          int B)
{
    extern __shared__ uint32_t sm[];
    float* smf = reinterpret_cast<float*>(sm);
    uint32_t* WpH = sm + WPHI_O;
    uint32_t* WpL = sm + WPLO_O;
    uint32_t* ovH = sm + OVHI_O;
    uint32_t* ovL = sm + OVLO_O;
    float* sWout  = smf + WOUT_O;
    float* sbout  = smf + BOUT_O;

    const int tid  = threadIdx.x;
    const int row0 = blockIdx.x * ROWS_PER_BLOCK;

    // ---- zero the ov slabs (pads beyond col 23 must be 0, not NaN) ----
    for (int i = tid; i < 2 * 16 * OVP; i += THREADS) ovH[i] = 0u;   // covers ovH+ovL (contiguous)
    if (tid < 72) sWout[tid] = W_out[tid];
    if (tid < 3)  sbout[tid] = b_out[tid];

    // ---- stage W: split to bf16 hi/lo, pack k-pairs, B-operand layout ----
    // Wp[k][n][p] = {hi16=bf16(W[k][2p+1][n]), lo16=bf16(W[k][2p][n])}, rows>=24 -> 0
    for (int idx = tid; idx < 16 * 24 * 16; idx += THREADS) {
        const int k = idx / 384, rem = idx % 384;
        const int n = rem / 16, p = rem % 16;
        const int r0 = 2 * p, r1 = 2 * p + 1;
        const float v0 = (r0 < 24) ? __ldg(&Ws[k * 576 + r0 * 24 + n]) : 0.0f;
        const float v1 = (r1 < 24) ? __ldg(&Ws[k * 576 + r1 * 24 + n]) : 0.0f;
        uint32_t h;  PACK_BF16X2(h, v1, v0);
        const float l0 = v0 - bf_lo_f32(h);
        const float l1 = v1 - bf_hi_f32(h);
        uint32_t l;  PACK_BF16X2(l, l1, l0);
        const int o = k * 480 + n * WNP + p;
        WpH[o] = h;
        WpL[o] = l;
    }
    __syncthreads();

    const int lane  = tid & 31;
    const int g     = lane >> 2;        // groupID
    const int t     = lane & 3;         // thread-in-group
    const int wbase = (tid >> 5) * 32;  // warp's first local row

    const float bt = __ldg(b_time), bc = __ldg(b_cost);
    const float a1 = __ldg(asc_train), a2 = __ldg(asc_sm), a3 = __ldg(asc_car);

    int rloc[4];
    rloc[0] = wbase + g;       rloc[1] = wbase + g + 8;
    rloc[2] = wbase + 16 + g;  rloc[3] = wbase + 24 + g;

    // global x row pointers (clamped for safety on tails)
    const float* xp[4];
    #pragma unroll
    for (int r = 0; r < 4; r++) {
        int grow = row0 + rloc[r];
        if (grow >= B) grow = B - 1;
        xp[r] = x + (size_t)grow * 27;
    }

    // state in C-fragment patch layout: row = rloc[m*2+(c>>1)], col = 8n+2t+(c&1)
    float ov[2][3][4], S[2][3][4];
    #pragma unroll
    for (int m = 0; m < 2; m++)
        #pragma unroll
        for (int n = 0; n < 3; n++)
            #pragma unroll
            for (int c = 0; c < 4; c++) {
                ov[m][n][c] = v_col(xp[m * 2 + (c >> 1)], 8 * n + 2 * t + (c & 1),
                                    bt, bc, a1, a2, a3);
                S[m][n][c] = 0.0f;
            }

    // ---- publish ov to hi/lo slabs (pairs = adjacent cols) ----
    auto publish = [&]() {
        #pragma unroll
        for (int m = 0; m < 2; m++)
            #pragma unroll
            for (int n = 0; n < 3; n++)
                #pragma unroll
                for (int s = 0; s < 2; s++) {
                    const int row = rloc[m * 2 + s];
                    const int pr  = 4 * n + t;
                    const float v0 = ov[m][n][s * 2 + 0];
                    const float v1 = ov[m][n][s * 2 + 1];
                    uint32_t h;  PACK_BF16X2(h, v1, v0);
                    const float l0 = v0 - bf_lo_f32(h);
                    const float l1 = v1 - bf_hi_f32(h);
                    uint32_t l;  PACK_BF16X2(l, l1, l0);
                    ovH[pr * OVP + row] = h;
                    ovL[pr * OVP + row] = l;
                }
    };
    publish();
    __syncwarp();

    // ---- 16-step scan ----
    #pragma unroll 1
    for (int k = 0; k < 16; k++) {
        const uint32_t* WkH = WpH + k * 480;
        const uint32_t* WkL = WpL + k * 480;

        float D[2][3][4];
        #pragma unroll
        for (int m = 0; m < 2; m++)
            #pragma unroll
            for (int n = 0; n < 3; n++)
                #pragma unroll
                for (int c = 0; c < 4; c++) D[m][n][c] = 0.0f;

        #pragma unroll
        for (int ch = 0; ch < 2; ch++) {
            uint32_t ah[2][4], al[2][4];
            const int p0 = ch * 8 + t, p1 = p0 + 4;
            #pragma unroll
            for (int m = 0; m < 2; m++) {
                const int ra = wbase + m * 16 + g;
                ah[m][0] = ovH[p0 * OVP + ra];
                ah[m][1] = ovH[p0 * OVP + ra + 8];
                ah[m][2] = ovH[p1 * OVP + ra];
                ah[m][3] = ovH[p1 * OVP + ra + 8];
                al[m][0] = ovL[p0 * OVP + ra];
                al[m][1] = ovL[p0 * OVP + ra + 8];
                al[m][2] = ovL[p1 * OVP + ra];
                al[m][3] = ovL[p1 * OVP + ra + 8];
            }
            #pragma unroll
            for (int n = 0; n < 3; n++) {
                const int bi = (8 * n + g) * WNP + ch * 8 + t;
                const uint32_t bh0 = WkH[bi], bh1 = WkH[bi + 4];
                const uint32_t bl0 = WkL[bi], bl1 = WkL[bi + 4];
                #pragma unroll
                for (int m = 0; m < 2; m++) {
                    mma_bf16(D[m][n], ah[m], bh0, bh1);   // hi*hi
                    mma_bf16(D[m][n], al[m], bh0, bh1);   // lo*hi
                    mma_bf16(D[m][n], ah[m], bl0, bl1);   // hi*lo
                }
            }
        }
        __syncwarp();

        // softplus + running-sum scan update
        #pragma unroll
        for (int m = 0; m < 2; m++)
            #pragma unroll
            for (int n = 0; n < 3; n++)
                #pragma unroll
                for (int c = 0; c < 4; c++) {
                    S[m][n][c] += softplus_fast(D[m][n][c]);
                    ov[m][n][c] -= S[m][n][c];
                }

        if (k < 15) {
            publish();
            __syncwarp();
        }
    }

    // ---- epilogue: U = V - S_16, softmax(24), @W_out + b_out, relu ----
    float u[2][3][4];
    #pragma unroll
    for (int m = 0; m < 2; m++)
        #pragma unroll
        for (int n = 0; n < 3; n++)
            #pragma unroll
            for (int c = 0; c < 4; c++)
                u[m][n][c] = v_col(xp[m * 2 + (c >> 1)], 8 * n + 2 * t + (c & 1),
                                   bt, bc, a1, a2, a3) - S[m][n][c];

    #pragma unroll
    for (int rr = 0; rr < 4; rr++) {
        const int m = rr >> 1, ch = rr & 1;

        float mx = -3.4e38f;
        #pragma unroll
        for (int n = 0; n < 3; n++)
            #pragma unroll
            for (int p = 0; p < 2; p++) mx = fmaxf(mx, u[m][n][ch * 2 + p]);
        mx = fmaxf(mx, __shfl_xor_sync(0xffffffffu, mx, 1));
        mx = fmaxf(mx, __shfl_xor_sync(0xffffffffu, mx, 2));

        float e[6], s = 0.0f;
        #pragma unroll
        for (int n = 0; n < 3; n++)
            #pragma unroll
            for (int p = 0; p < 2; p++) {
                const float ev = exp_fast(u[m][n][ch * 2 + p] - mx);
                e[n * 2 + p] = ev;
                s += ev;
            }
        s += __shfl_xor_sync(0xffffffffu, s, 1);
        s += __shfl_xor_sync(0xffffffffu, s, 2);
        const float inv = rcp_fast(s);

        float d0 = 0.0f, d1 = 0.0f, d2 = 0.0f;
        #pragma unroll
        for (int n = 0; n < 3; n++)
            #pragma unroll
            for (int p = 0; p < 2; p++) {
                const int col = 8 * n + 2 * t + p;
                const float ev = e[n * 2 + p];
                d0 = fmaf(ev, sWout[col * 3 + 0], d0);
                d1 = fmaf(ev, sWout[col * 3 + 1], d1);
                d2 = fmaf(ev, sWout[col * 3 + 2], d2);
            }
        d0 += __shfl_xor_sync(0xffffffffu, d0, 1);
        d0 += __shfl_xor_sync(0xffffffffu, d0, 2);
        d1 += __shfl_xor_sync(0xffffffffu, d1, 1);
        d1 += __shfl_xor_sync(0xffffffffu, d1, 2);
        d2 += __shfl_xor_sync(0xffffffffu, d2, 1);
        d2 += __shfl_xor_sync(0xffffffffu, d2, 2);

        if (t == 0) {
            const int grow = row0 + rloc[rr];
            if (grow < B) {
                float* op = out + (size_t)grow * 3;
                op[0] = fmaxf(fmaf(d0, inv, sbout[0]), 0.0f);
                op[1] = fmaxf(fmaf(d1, inv, sbout[1]), 0.0f);
                op[2] = fmaxf(fmaf(d2, inv, sbout[2]), 0.0f);
            }
        }
    }
}

extern "C" void kernel_launch(void* const* d_in, const int* in_sizes, int n_in,
                              void* d_out, int out_size)
{
    const float* x         = (const float*)d_in[0];
    const float* asc_train = (const float*)d_in[1];
    const float* asc_sm    = (const float*)d_in[2];
    const float* asc_car   = (const float*)d_in[3];
    const float* b_time    = (const float*)d_in[4];
    const float* b_cost    = (const float*)d_in[5];
    const float* Ws        = (const float*)d_in[6];
    const float* W_out     = (const float*)d_in[7];
    const float* b_out     = (const float*)d_in[8];
    float* out = (float*)d_out;

    const int B = in_sizes[0] / 27;
    const int smem_bytes = SMEM_WORDS * 4;

    cudaFuncSetAttribute(reslogit_bf16_kernel,
                         cudaFuncAttributeMaxDynamicSharedMemorySize, smem_bytes);

    const int grid = (B + ROWS_PER_BLOCK - 1) / ROWS_PER_BLOCK;
    reslogit_bf16_kernel<<<grid, THREADS, smem_bytes>>>(
        x, asc_train, asc_sm, asc_car, b_time, b_cost, Ws, W_out, b_out, out, B);
}

// round 11
// speedup vs baseline: 2.4374x; 1.4130x over previous
#include <cuda_runtime.h>
#include <cstdint>

#define THREADS 256
#define ROWS_PER_BLOCK 256
#define P 20                 // pitch (words) for W and ov slabs: conflict-free patterns

// ---- smem word offsets ----
#define W_O     0                          // fp16x2 pairs: [k][nrow*P + pair], 16*24*P... rows padded
#define W_WORDS (16 * 24 * P)              // 7680
#define SLAB_O  W_WORDS                    // ov slab fp16x2: [row*P + pair], 256 rows
#define SLAB_WORDS (ROWS_PER_BLOCK * P)    // 5120
#define WOUT_O  (SLAB_O + SLAB_WORDS)      // 24*3 f32
#define BOUT_O  (WOUT_O + 72)
#define SMEM_WORDS (BOUT_O + 4)            // 12876 words = 51,504 B

// ---- fast transcendentals (MUFU pipe) ----
__device__ __forceinline__ float softplus_fast(float x) {
    float e, l;
    float y = fabsf(x) * -1.4426950408889634f;
    asm("ex2.approx.f32 %0, %1;" : "=f"(e) : "f"(y));
    float u = 1.0f + e;
    asm("lg2.approx.f32 %0, %1;" : "=f"(l) : "f"(u));
    return fmaxf(x, 0.0f) + l * 0.6931471805599453f;
}
__device__ __forceinline__ float exp_fast(float x) {
    float e;
    asm("ex2.approx.f32 %0, %1;" : "=f"(e) : "f"(x * 1.4426950408889634f));
    return e;
}
__device__ __forceinline__ float rcp_fast(float x) {
    float r;
    asm("rcp.approx.f32 %0, %1;" : "=f"(r) : "f"(x));
    return r;
}

// pack two f32 -> f16x2 {hi=vh, lo=vl}
#define PACK_F16X2(d, vh, vl) \
    asm("cvt.rn.f16x2.f32 %0, %1, %2;" : "=r"(d) : "f"(vh), "f"(vl))

// m16n8k16 fp16 MMA, f32 accumulate in place
__device__ __forceinline__ void mma_f16(float* d, const uint32_t* a,
                                        uint32_t b0, uint32_t b1) {
    asm volatile(
        "mma.sync.aligned.m16n8k16.row.col.f32.f16.f16.f32 "
        "{%0,%1,%2,%3}, {%4,%5,%6,%7}, {%8,%9}, {%0,%1,%2,%3};"
        : "+f"(d[0]), "+f"(d[1]), "+f"(d[2]), "+f"(d[3])
        : "r"(a[0]), "r"(a[1]), "r"(a[2]), "r"(a[3]), "r"(b0), "r"(b1));
}

#define LDMATRIX_X4(a, addr) \
    asm volatile("ldmatrix.sync.aligned.m8n8.x4.shared.b16 {%0,%1,%2,%3}, [%4];" \
        : "=r"((a)[0]), "=r"((a)[1]), "=r"((a)[2]), "=r"((a)[3]) : "r"(addr))

__device__ __forceinline__ uint32_t smem_u32(const void* p) {
    uint32_t a;
    asm("{ .reg .u64 t; cvta.to.shared.u64 t, %1; cvt.u32.u64 %0, t; }" : "=r"(a) : "l"(p));
    return a;
}

// V element for (global row, col)
__device__ __forceinline__ float v_col(const float* __restrict__ xr, int col,
                                       float bt, float bc,
                                       float a1, float a2, float a3) {
    if (col < 19) return __ldg(&xr[col]);
    if (col == 19) return __ldg(&xr[21]);
    if (col == 20) return __ldg(&xr[24]);
    if (col == 21) return fmaf(bc, __ldg(&xr[20]), fmaf(bt, __ldg(&xr[19]), a1));
    if (col == 22) return fmaf(bc, __ldg(&xr[23]), fmaf(bt, __ldg(&xr[22]), a2));
    return fmaf(bc, __ldg(&xr[26]), fmaf(bt, __ldg(&xr[25]), a3));
}

__global__ __launch_bounds__(THREADS, 2)
void reslogit_f16_kernel(const float* __restrict__ x,
                         const float* __restrict__ asc_train,
                         const float* __restrict__ asc_sm,
                         const float* __restrict__ asc_car,
                         const float* __restrict__ b_time,
                         const float* __restrict__ b_cost,
                         const float* __restrict__ Ws,
                         const float* __restrict__ W_out,
                         const float* __restrict__ b_out,
                         float* __restrict__ out,
                         int B)
{
    extern __shared__ uint32_t sm[];
    float* smf   = reinterpret_cast<float*>(sm);
    uint32_t* Wp = sm + W_O;
    uint32_t* sl = sm + SLAB_O;
    float* sWout = smf + WOUT_O;
    float* sbout = smf + BOUT_O;

    const int tid  = threadIdx.x;
    const int row0 = blockIdx.x * ROWS_PER_BLOCK;

    // ---- zero ov slab (pads beyond pair 11 stay 0) ----
    for (int i = tid; i < SLAB_WORDS; i += THREADS) sl[i] = 0u;
    if (tid < 72) sWout[tid] = W_out[tid];
    if (tid < 3)  sbout[tid] = b_out[tid];

    // ---- stage W as fp16 k-pairs, B-operand (col-major-K) layout ----
    // Wp[k][nrow*P + p] = {hi=f16(W[k][2p+1][nrow]), lo=f16(W[k][2p][nrow])}, p>=12 -> 0
    for (int idx = tid; idx < 16 * 24 * 16; idx += THREADS) {
        const int k = idx / 384, rem = idx % 384;
        const int nrow = rem / 16, p = rem % 16;
        const int r0 = 2 * p, r1 = 2 * p + 1;
        const float v0 = (r0 < 24) ? __ldg(&Ws[k * 576 + r0 * 24 + nrow]) : 0.0f;
        const float v1 = (r1 < 24) ? __ldg(&Ws[k * 576 + r1 * 24 + nrow]) : 0.0f;
        uint32_t h;  PACK_F16X2(h, v1, v0);
        Wp[k * (24 * P) + nrow * P + p] = h;
    }
    __syncthreads();

    const int lane  = tid & 31;
    const int g     = lane >> 2;        // groupID
    const int t     = lane & 3;         // thread-in-group
    const int wbase = (tid >> 5) * 32;  // warp's first local row

    const float bt = __ldg(b_time), bc = __ldg(b_cost);
    const float a1 = __ldg(asc_train), a2 = __ldg(asc_sm), a3 = __ldg(asc_car);

    int rloc[4];
    rloc[0] = wbase + g;       rloc[1] = wbase + g + 8;
    rloc[2] = wbase + 16 + g;  rloc[3] = wbase + 24 + g;

    // global x row pointers (clamped on tail; outputs guarded later)
    const float* xp[4];
    #pragma unroll
    for (int r = 0; r < 4; r++) {
        int grow = row0 + rloc[r];
        if (grow >= B) grow = B - 1;
        xp[r] = x + (size_t)grow * 27;
    }

    // ldmatrix per-lane addresses for (m, ch), k-invariant
    const uint32_t sbase = smem_u32(sm);
    uint32_t lm_addr[2][2];
    {
        const int tile = lane >> 3, rit = lane & 7;
        #pragma unroll
        for (int m = 0; m < 2; m++)
            #pragma unroll
            for (int ch = 0; ch < 2; ch++) {
                const int row  = wbase + m * 16 + (tile & 1) * 8 + rit;
                const int word = SLAB_O + row * P + ch * 8 + (tile >> 1) * 4;
                lm_addr[m][ch] = sbase + word * 4;
            }
    }

    // state in C-fragment patch layout: row = rloc[m*2+(c>>1)], col = 8n+2t+(c&1)
    float ov[2][3][4], S[2][3][4];
    #pragma unroll
    for (int m = 0; m < 2; m++)
        #pragma unroll
        for (int n = 0; n < 3; n++)
            #pragma unroll
            for (int c = 0; c < 4; c++) {
                ov[m][n][c] = v_col(xp[m * 2 + (c >> 1)], 8 * n + 2 * t + (c & 1),
                                    bt, bc, a1, a2, a3);
                S[m][n][c] = 0.0f;
            }

    // publish ov (fp16 pairs) to slab: pair pr = 4n+t at row rloc
    auto publish = [&]() {
        #pragma unroll
        for (int m = 0; m < 2; m++)
            #pragma unroll
            for (int n = 0; n < 3; n++)
                #pragma unroll
                for (int s = 0; s < 2; s++) {
                    const int row = rloc[m * 2 + s];
                    uint32_t h;
                    PACK_F16X2(h, ov[m][n][s * 2 + 1], ov[m][n][s * 2 + 0]);
                    sl[row * P + 4 * n + t] = h;
                }
    };
    publish();
    __syncwarp();

    // ---- 16-step scan ----
    #pragma unroll 1
    for (int k = 0; k < 16; k++) {
        const uint32_t* Wk = Wp + k * (24 * P);

        float D[2][3][4];
        #pragma unroll
        for (int m = 0; m < 2; m++)
            #pragma unroll
            for (int n = 0; n < 3; n++)
                #pragma unroll
                for (int c = 0; c < 4; c++) D[m][n][c] = 0.0f;

        #pragma unroll
        for (int ch = 0; ch < 2; ch++) {
            uint32_t a0[4], a1f[4];
            LDMATRIX_X4(a0,  lm_addr[0][ch]);
            LDMATRIX_X4(a1f, lm_addr[1][ch]);
            #pragma unroll
            for (int n = 0; n < 3; n++) {
                const int bi = (8 * n + g) * P + ch * 8 + t;
                const uint32_t b0 = Wk[bi], b1 = Wk[bi + 4];
                mma_f16(D[0][n], a0,  b0, b1);
                mma_f16(D[1][n], a1f, b0, b1);
            }
        }
        __syncwarp();

        // softplus + running-sum scan update (ov_k = ov_{k-1} - S_k)
        #pragma unroll
        for (int m = 0; m < 2; m++)
            #pragma unroll
            for (int n = 0; n < 3; n++)
                #pragma unroll
                for (int c = 0; c < 4; c++) {
                    S[m][n][c] += softplus_fast(D[m][n][c]);
                    ov[m][n][c] -= S[m][n][c];
                }

        if (k < 15) {
            publish();
            __syncwarp();
        }
    }

    // ---- epilogue: U = V - S_16, softmax(24), @W_out + b_out, relu ----
    float u[2][3][4];
    #pragma unroll
    for (int m = 0; m < 2; m++)
        #pragma unroll
        for (int n = 0; n < 3; n++)
            #pragma unroll
            for (int c = 0; c < 4; c++)
                u[m][n][c] = v_col(xp[m * 2 + (c >> 1)], 8 * n + 2 * t + (c & 1),
                                   bt, bc, a1, a2, a3) - S[m][n][c];

    #pragma unroll
    for (int rr = 0; rr < 4; rr++) {
        const int m = rr >> 1, ch = rr & 1;

        float mx = -3.4e38f;
        #pragma unroll
        for (int n = 0; n < 3; n++)
            #pragma unroll
            for (int p = 0; p < 2; p++) mx = fmaxf(mx, u[m][n][ch * 2 + p]);
        mx = fmaxf(mx, __shfl_xor_sync(0xffffffffu, mx, 1));
        mx = fmaxf(mx, __shfl_xor_sync(0xffffffffu, mx, 2));

        float e[6], s = 0.0f;
        #pragma unroll
        for (int n = 0; n < 3; n++)
            #pragma unroll
            for (int p = 0; p < 2; p++) {
                const float ev = exp_fast(u[m][n][ch * 2 + p] - mx);
                e[n * 2 + p] = ev;
                s += ev;
            }
        s += __shfl_xor_sync(0xffffffffu, s, 1);
        s += __shfl_xor_sync(0xffffffffu, s, 2);
        const float inv = rcp_fast(s);

        float d0 = 0.0f, d1 = 0.0f, d2 = 0.0f;
        #pragma unroll
        for (int n = 0; n < 3; n++)
            #pragma unroll
            for (int p = 0; p < 2; p++) {
                const int col = 8 * n + 2 * t + p;
                const float ev = e[n * 2 + p];
                d0 = fmaf(ev, sWout[col * 3 + 0], d0);
                d1 = fmaf(ev, sWout[col * 3 + 1], d1);
                d2 = fmaf(ev, sWout[col * 3 + 2], d2);
            }
        d0 += __shfl_xor_sync(0xffffffffu, d0, 1);
        d0 += __shfl_xor_sync(0xffffffffu, d0, 2);
        d1 += __shfl_xor_sync(0xffffffffu, d1, 1);
        d1 += __shfl_xor_sync(0xffffffffu, d1, 2);
        d2 += __shfl_xor_sync(0xffffffffu, d2, 1);
        d2 += __shfl_xor_sync(0xffffffffu, d2, 2);

        if (t == 0) {
            const int grow = row0 + rloc[rr];
            if (grow < B) {
                float* op = out + (size_t)grow * 3;
                op[0] = fmaxf(fmaf(d0, inv, sbout[0]), 0.0f);
                op[1] = fmaxf(fmaf(d1, inv, sbout[1]), 0.0f);
                op[2] = fmaxf(fmaf(d2, inv, sbout[2]), 0.0f);
            }
        }
    }
}

extern "C" void kernel_launch(void* const* d_in, const int* in_sizes, int n_in,
                              void* d_out, int out_size)
{
    const float* x         = (const float*)d_in[0];
    const float* asc_train = (const float*)d_in[1];
    const float* asc_sm    = (const float*)d_in[2];
    const float* asc_car   = (const float*)d_in[3];
    const float* b_time    = (const float*)d_in[4];
    const float* b_cost    = (const float*)d_in[5];
    const float* Ws        = (const float*)d_in[6];
    const float* W_out     = (const float*)d_in[7];
    const float* b_out     = (const float*)d_in[8];
    float* out = (float*)d_out;

    const int B = in_sizes[0] / 27;
    const int smem_bytes = SMEM_WORDS * 4;

    cudaFuncSetAttribute(reslogit_f16_kernel,
                         cudaFuncAttributeMaxDynamicSharedMemorySize, smem_bytes);

    const int grid = (B + ROWS_PER_BLOCK - 1) / ROWS_PER_BLOCK;
    reslogit_f16_kernel<<<grid, THREADS, smem_bytes>>>(
        x, asc_train, asc_sm, asc_car, b_time, b_cost, Ws, W_out, b_out, out, B);
}